// round 7
// baseline (speedup 1.0000x reference)
#include <cuda_runtime.h>
#include <math.h>

#define BATCH 4096
#define IN_DIM 512
#define HD1 1024
#define HD2 512
#define NC 50
#define NE 8
#define TM 32                       // token-tile rows per block
#define MAXBLK 264                  // ceil((BATCH*2 + NE*31)/TM)
#define NSLOT (MAXBLK*TM)

// ---------------- small scratch only (~70 KB module data total) -------------
__device__ int   g_count[NE];
__device__ int   g_cursor[NE];
__device__ int   g_offset[NE];      // padded exclusive offsets (multiples of 32)
__device__ int   g_slot_token[NSLOT];
__device__ float g_slot_gate[NSLOT];
__device__ int   g_topk_idx[BATCH*2];
__device__ float g_topk_val[BATCH*2];

// ---------------- init ------------------------------------------------------
__global__ void init_kernel() {
    int i = threadIdx.x;
    if (i < NE) { g_count[i] = 0; g_cursor[i] = 0; }
}

// ---------------- zero the combined-output region ---------------------------
__global__ void zero_out_kernel(float* __restrict__ out) {
    int i = blockIdx.x * blockDim.x + threadIdx.x;
    if (i < BATCH * NC) out[i] = 0.f;
}

// ---------------- router: logits, softmax, top-2, counts --------------------
__global__ void router_kernel(const float* __restrict__ x,
                              const float* __restrict__ Wr,
                              const float* __restrict__ br,
                              float* __restrict__ probs_out) {
    int gwarp = (blockIdx.x * blockDim.x + threadIdx.x) >> 5;
    int lane  = threadIdx.x & 31;
    if (gwarp >= BATCH) return;
    const float* xr = x + (size_t)gwarp * IN_DIM;

    float acc[NE];
#pragma unroll
    for (int e = 0; e < NE; e++) acc[e] = 0.f;
    for (int k = lane; k < IN_DIM; k += 32) {
        float xv = xr[k];
        const float* w = Wr + (size_t)k * NE;
#pragma unroll
        for (int e = 0; e < NE; e++) acc[e] += xv * w[e];
    }
#pragma unroll
    for (int e = 0; e < NE; e++) {
#pragma unroll
        for (int o = 16; o > 0; o >>= 1)
            acc[e] += __shfl_xor_sync(0xffffffff, acc[e], o);
    }
    if (lane == 0) {
        float lg[NE], p[NE];
        float mx = -1e30f;
#pragma unroll
        for (int e = 0; e < NE; e++) { lg[e] = acc[e] + br[e]; mx = fmaxf(mx, lg[e]); }
        float s = 0.f;
#pragma unroll
        for (int e = 0; e < NE; e++) { p[e] = __expf(lg[e] - mx); s += p[e]; }
        float inv = 1.f / s;
#pragma unroll
        for (int e = 0; e < NE; e++) {
            p[e] *= inv;
            probs_out[(size_t)gwarp * NE + e] = p[e];
        }
        int i0 = 0; float v0 = p[0];
#pragma unroll
        for (int e = 1; e < NE; e++) if (p[e] > v0) { v0 = p[e]; i0 = e; }
        int i1 = -1; float v1 = -1e30f;
#pragma unroll
        for (int e = 0; e < NE; e++) if (e != i0 && p[e] > v1) { v1 = p[e]; i1 = e; }
        i1 = i1 < 0 ? 0 : i1;

        g_topk_idx[gwarp*2+0] = i0; g_topk_val[gwarp*2+0] = v0;
        g_topk_idx[gwarp*2+1] = i1; g_topk_val[gwarp*2+1] = v1;
        atomicAdd(&g_count[i0], 1);
        atomicAdd(&g_count[i1], 1);
    }
}

// ---------------- padded exclusive scan -------------------------------------
__global__ void offsets_kernel() {
    int o = 0;
    for (int e = 0; e < NE; e++) {
        g_offset[e] = o;
        o += (g_count[e] + TM - 1) & ~(TM - 1);
    }
}

// ---------------- fill per-expert slot lists --------------------------------
__global__ void fill_kernel() {
    int t = blockIdx.x * blockDim.x + threadIdx.x;
    if (t >= BATCH) return;
#pragma unroll
    for (int k = 0; k < 2; k++) {
        int e = g_topk_idx[t*2+k] & 7;
        int pos = atomicAdd(&g_cursor[e], 1);
        int slot = g_offset[e] + pos;
        g_slot_token[slot] = t;
        g_slot_gate[slot]  = g_topk_val[t*2+k];
    }
}

// ---------------- fused expert MLP ------------------------------------------
// One block = 32 token-slots of one expert. h1/h2 tiles live in smem.
//   smem layout (floats):  h1s[1024][33]  | xh[512][33] (xs then h2s) | ws
#define H1S_STRIDE 33
#define XH_STRIDE  33
#define WS_FLOATS  (CHK_MAX*132)
#define CHK_MAX    32
#define SMEM_H1S   0
#define SMEM_XH    (1024*H1S_STRIDE)
#define SMEM_WS    (SMEM_XH + 512*XH_STRIDE)
#define SMEM_TOTALF (SMEM_WS + WS_FLOATS)

__global__ void __launch_bounds__(256, 1)
fused_expert_kernel(const float* __restrict__ x,
                    const float* __restrict__ W1, const float* __restrict__ b1,
                    const float* __restrict__ W2, const float* __restrict__ b2,
                    const float* __restrict__ W3, const float* __restrict__ b3,
                    float* __restrict__ out) {
    extern __shared__ float sm[];
    float* h1s = sm + SMEM_H1S;     // [n][m] n<1024, stride 33
    float* xh  = sm + SMEM_XH;      // [k][m] k<512,  stride 33 (xs, then h2s)
    float* ws  = sm + SMEM_WS;      // staging

    const int tid = threadIdx.x;
    const int tx = tid & 31, ty = tid >> 5;
    const int slot0 = blockIdx.x * TM;

    // locate expert segment
    int e = -1, cnt = 0;
#pragma unroll
    for (int ee = 0; ee < NE; ee++) {
        int off = g_offset[ee];
        int pc  = (g_count[ee] + TM - 1) & ~(TM - 1);
        if (slot0 >= off && slot0 < off + pc) { e = ee; cnt = g_count[ee]; }
    }
    if (e < 0) return;
    const int local0 = slot0 - g_offset[e];
    const int rowsv  = min(TM, cnt - local0);     // >=1 by construction

    // ---- load gathered x tile into xh[k][m] (transposed, padded) ----
    for (int idx = tid; idx < TM * (IN_DIM/4); idx += 256) {
        int r = idx / (IN_DIM/4);
        int c4 = idx % (IN_DIM/4);
        float4 v = make_float4(0.f,0.f,0.f,0.f);
        if (r < rowsv) {
            int tok = g_slot_token[slot0 + r];
            v = *(const float4*)(x + (size_t)tok * IN_DIM + c4*4);
        }
        xh[(c4*4+0)*XH_STRIDE + r] = v.x;
        xh[(c4*4+1)*XH_STRIDE + r] = v.y;
        xh[(c4*4+2)*XH_STRIDE + r] = v.z;
        xh[(c4*4+3)*XH_STRIDE + r] = v.w;
    }
    __syncthreads();

    const float* W1e = W1 + (size_t)e * IN_DIM * HD1;
    const float* W2e = W2 + (size_t)e * HD1 * HD2;

    // ---- stage A: h1s[n][m] = relu(x @ W1 + b1), n-chunks of 128 ----
    for (int n0 = 0; n0 < HD1; n0 += 128) {
        float acc[4][4] = {};
        for (int k0 = 0; k0 < IN_DIM; k0 += 32) {
            // stage W1[k0:+32, n0:+128] -> ws[kr][c] stride 132
            for (int i = 0; i < 4; i++) {
                int lin = tid + i*256;            // 1024 float4
                int kr = lin >> 5, c4 = lin & 31;
                float4 v = *(const float4*)(W1e + (size_t)(k0+kr)*HD1 + n0 + c4*4);
                *(float4*)(ws + kr*132 + c4*4) = v;
            }
            __syncthreads();
#pragma unroll
            for (int kk = 0; kk < 32; kk++) {
                float a[4];
#pragma unroll
                for (int i = 0; i < 4; i++) a[i] = xh[(k0+kk)*XH_STRIDE + ty*4+i];
                float4 b4 = *(const float4*)(ws + kk*132 + tx*4);
#pragma unroll
                for (int i = 0; i < 4; i++) {
                    acc[i][0] += a[i] * b4.x;
                    acc[i][1] += a[i] * b4.y;
                    acc[i][2] += a[i] * b4.z;
                    acc[i][3] += a[i] * b4.w;
                }
            }
            __syncthreads();
        }
        const float* bb = b1 + (size_t)e * HD1 + n0;
#pragma unroll
        for (int j = 0; j < 4; j++) {
            float bj = bb[tx*4+j];
#pragma unroll
            for (int i = 0; i < 4; i++)
                h1s[(n0+tx*4+j)*H1S_STRIDE + ty*4+i] = fmaxf(acc[i][j] + bj, 0.f);
        }
    }
    __syncthreads();

    // ---- stage B: h2 (into xh region)[n][m] = relu(h1 @ W2 + b2) ----
    for (int n0 = 0; n0 < HD2; n0 += 128) {
        float acc[4][4] = {};
        for (int k0 = 0; k0 < HD1; k0 += 32) {
            for (int i = 0; i < 4; i++) {
                int lin = tid + i*256;
                int kr = lin >> 5, c4 = lin & 31;
                float4 v = *(const float4*)(W2e + (size_t)(k0+kr)*HD2 + n0 + c4*4);
                *(float4*)(ws + kr*132 + c4*4) = v;
            }
            __syncthreads();
#pragma unroll
            for (int kk = 0; kk < 32; kk++) {
                float a[4];
#pragma unroll
                for (int i = 0; i < 4; i++) a[i] = h1s[(k0+kk)*H1S_STRIDE + ty*4+i];
                float4 b4 = *(const float4*)(ws + kk*132 + tx*4);
#pragma unroll
                for (int i = 0; i < 4; i++) {
                    acc[i][0] += a[i] * b4.x;
                    acc[i][1] += a[i] * b4.y;
                    acc[i][2] += a[i] * b4.z;
                    acc[i][3] += a[i] * b4.w;
                }
            }
            __syncthreads();
        }
        const float* bb = b2 + (size_t)e * HD2 + n0;
#pragma unroll
        for (int j = 0; j < 4; j++) {
            float bj = bb[tx*4+j];
#pragma unroll
            for (int i = 0; i < 4; i++)
                xh[(n0+tx*4+j)*XH_STRIDE + ty*4+i] = fmaxf(acc[i][j] + bj, 0.f);
        }
        __syncthreads();   // ws reuse + xh now holds h2 for these cols
    }

    // ---- stage C: eo[m][c] = h2 @ W3 + b3; combine into out via atomicAdd --
    const float* W3e = W3 + (size_t)e * HD2 * NC;
    float accC[7];
#pragma unroll
    for (int j = 0; j < 7; j++) accC[j] = 0.f;

    for (int k0 = 0; k0 < HD2; k0 += 64) {
        // stage W3[k0:+64, 0:50] -> ws[kr*52 + c]
        for (int idx = tid; idx < 64*NC; idx += 256) {
            int kr = idx / NC, c = idx % NC;
            ws[kr*52 + c] = W3e[(size_t)(k0+kr)*NC + c];
        }
        __syncthreads();
        for (int j = 0; j < 7; j++) {
            int oi = tid + j*256;
            if (oi < TM*NC) {
                int r = oi / NC, c = oi % NC;
                float s = 0.f;
#pragma unroll 8
                for (int kk = 0; kk < 64; kk++)
                    s += xh[(k0+kk)*XH_STRIDE + r] * ws[kk*52 + c];
                accC[j] += s;
            }
        }
        __syncthreads();
    }
    const float* b3e = b3 + (size_t)e * NC;
#pragma unroll
    for (int j = 0; j < 7; j++) {
        int oi = tid + j*256;
        if (oi < TM*NC) {
            int r = oi / NC, c = oi % NC;
            if (r < rowsv) {
                int tok  = g_slot_token[slot0 + r];
                float v  = g_slot_gate[slot0 + r];
                float eo = accC[j] + b3e[c];
                atomicAdd(&out[(size_t)tok*NC + c], 0.5f * v * eo);
            }
        }
    }
}

// ---------------- launch ----------------------------------------------------
extern "C" void kernel_launch(void* const* d_in, const int* in_sizes, int n_in,
                              void* d_out, int out_size) {
    // Bind inputs BY SIZE (robust to metadata ordering); collision pairs
    // {Wr,b2}=4096 and {W1,W2}=4194304 resolved by first-occurrence, which is
    // correct under both dict-insertion and alphabetical orderings.
    const float* x  = 0; const float* Wr = 0; const float* br = 0;
    const float* W1 = 0; const float* b1 = 0; const float* W2 = 0;
    const float* b2 = 0; const float* W3 = 0; const float* b3 = 0;
    int seen4096 = 0, seen4m = 0;
    for (int i = 0; i < n_in; i++) {
        const float* p = (const float*)d_in[i];
        switch (in_sizes[i]) {
            case 2097152: x  = p; break;
            case 8:       br = p; break;
            case 8192:    b1 = p; break;
            case 204800:  W3 = p; break;
            case 400:     b3 = p; break;
            case 4096:    if (seen4096++ == 0) Wr = p; else b2 = p; break;
            case 4194304: if (seen4m++   == 0) W1 = p; else W2 = p; break;
        }
    }

    float* out       = (float*)d_out;                 // [4096, 50]
    float* out_probs = out + (size_t)BATCH * NC;      // [4096, 8]

    // Unconditional (no static guard — harness forbids call-count state).
    cudaFuncSetAttribute(fused_expert_kernel,
                         cudaFuncAttributeMaxDynamicSharedMemorySize,
                         SMEM_TOTALF * (int)sizeof(float));

    init_kernel<<<1, 32>>>();
    router_kernel<<<BATCH/8, 256>>>(x, Wr, br, out_probs);
    offsets_kernel<<<1, 1>>>();
    fill_kernel<<<(BATCH + 255)/256, 256>>>();
    zero_out_kernel<<<(BATCH*NC + 255)/256, 256>>>(out);
    fused_expert_kernel<<<MAXBLK, 256, SMEM_TOTALF * sizeof(float)>>>(
        x, W1, b1, W2, b2, W3, b3, out);
}

// round 8
// speedup vs baseline: 1.3091x; 1.3091x over previous
#include <cuda_runtime.h>

#define BATCH 4096
#define IN_DIM 512
#define HD1 1024
#define HD2 512
#define NC 50
#define NE 8
#define TM 32                       // token-tile rows per block
#define MAXBLK 264                  // ceil((BATCH*2 + NE*31)/TM)
#define NSLOT (MAXBLK*TM)
#define KCH 8                       // k-chunk for weight staging

typedef unsigned long long ull;

// ---------------- packed f32x2 helpers (sm_100a FFMA2 path) -----------------
__device__ __forceinline__ ull splat2(float v) {
    ull r; asm("mov.b64 %0, {%1, %1};" : "=l"(r) : "f"(v)); return r;
}
__device__ __forceinline__ void ffma2(ull& d, ull a, ull b) {
    asm("fma.rn.f32x2 %0, %1, %2, %0;" : "+l"(d) : "l"(a), "l"(b));
}
__device__ __forceinline__ void unpack2(float& lo, float& hi, ull v) {
    asm("mov.b64 {%0, %1}, %2;" : "=f"(lo), "=f"(hi) : "l"(v));
}

// ---------------- small scratch only (~70 KB module data total) -------------
__device__ int   g_count[NE];
__device__ int   g_cursor[NE];
__device__ int   g_offset[NE];
__device__ int   g_slot_token[NSLOT];
__device__ float g_slot_gate[NSLOT];
__device__ int   g_topk_idx[BATCH*2];
__device__ float g_topk_val[BATCH*2];

// ---------------- init ------------------------------------------------------
__global__ void init_kernel() {
    int i = threadIdx.x;
    if (i < NE) { g_count[i] = 0; g_cursor[i] = 0; }
}

__global__ void zero_out_kernel(float* __restrict__ out) {
    int i = blockIdx.x * blockDim.x + threadIdx.x;
    if (i < BATCH * NC) out[i] = 0.f;
}

// ---------------- router: logits, softmax, top-2, counts --------------------
__global__ void router_kernel(const float* __restrict__ x,
                              const float* __restrict__ Wr,
                              const float* __restrict__ br,
                              float* __restrict__ probs_out) {
    int gwarp = (blockIdx.x * blockDim.x + threadIdx.x) >> 5;
    int lane  = threadIdx.x & 31;
    if (gwarp >= BATCH) return;
    const float* xr = x + (size_t)gwarp * IN_DIM;

    float acc[NE];
#pragma unroll
    for (int e = 0; e < NE; e++) acc[e] = 0.f;
    for (int k = lane; k < IN_DIM; k += 32) {
        float xv = xr[k];
        const float* w = Wr + (size_t)k * NE;
#pragma unroll
        for (int e = 0; e < NE; e++) acc[e] += xv * w[e];
    }
#pragma unroll
    for (int e = 0; e < NE; e++) {
#pragma unroll
        for (int o = 16; o > 0; o >>= 1)
            acc[e] += __shfl_xor_sync(0xffffffff, acc[e], o);
    }
    if (lane == 0) {
        float lg[NE], p[NE];
        float mx = -1e30f;
#pragma unroll
        for (int e = 0; e < NE; e++) { lg[e] = acc[e] + br[e]; mx = fmaxf(mx, lg[e]); }
        float s = 0.f;
#pragma unroll
        for (int e = 0; e < NE; e++) { p[e] = __expf(lg[e] - mx); s += p[e]; }
        float inv = 1.f / s;
#pragma unroll
        for (int e = 0; e < NE; e++) {
            p[e] *= inv;
            probs_out[(size_t)gwarp * NE + e] = p[e];
        }
        int i0 = 0; float v0 = p[0];
#pragma unroll
        for (int e = 1; e < NE; e++) if (p[e] > v0) { v0 = p[e]; i0 = e; }
        int i1 = -1; float v1 = -1e30f;
#pragma unroll
        for (int e = 0; e < NE; e++) if (e != i0 && p[e] > v1) { v1 = p[e]; i1 = e; }
        i1 = i1 < 0 ? 0 : i1;

        g_topk_idx[gwarp*2+0] = i0; g_topk_val[gwarp*2+0] = v0;
        g_topk_idx[gwarp*2+1] = i1; g_topk_val[gwarp*2+1] = v1;
        atomicAdd(&g_count[i0], 1);
        atomicAdd(&g_count[i1], 1);
    }
}

__global__ void offsets_kernel() {
    int o = 0;
    for (int e = 0; e < NE; e++) {
        g_offset[e] = o;
        o += (g_count[e] + TM - 1) & ~(TM - 1);
    }
}

__global__ void fill_kernel() {
    int t = blockIdx.x * blockDim.x + threadIdx.x;
    if (t >= BATCH) return;
#pragma unroll
    for (int k = 0; k < 2; k++) {
        int e = g_topk_idx[t*2+k] & 7;
        int pos = atomicAdd(&g_cursor[e], 1);
        int slot = g_offset[e] + pos;
        g_slot_token[slot] = t;
        g_slot_gate[slot]  = g_topk_val[t*2+k];
    }
}

// ---------------- fused expert MLP (FFMA2 mainloop) --------------------------
// One block = 32 token-slots of one expert. Layouts (floats, even strides so
// float2 smem loads are 8B-aligned):
//   h1s[1024][34]  (h1, [n][m])
//   xh [512][34]   (x then h2, [k][m])
//   ws [KCH*512]   (weight staging; also stage-C 64x52 staging)
#define H1S_STRIDE 34
#define XH_STRIDE  34
#define SMEM_H1S   0
#define SMEM_XH    (1024*H1S_STRIDE)
#define SMEM_WS    (SMEM_XH + 512*XH_STRIDE)
#define WS_FLOATS  (KCH*512)
#define SMEM_TOTALF (SMEM_WS + WS_FLOATS)

__global__ void __launch_bounds__(256, 1)
fused_expert_kernel(const float* __restrict__ x,
                    const float* __restrict__ W1, const float* __restrict__ b1,
                    const float* __restrict__ W2, const float* __restrict__ b2,
                    const float* __restrict__ W3, const float* __restrict__ b3,
                    float* __restrict__ out) {
    extern __shared__ float sm[];
    float* h1s = sm + SMEM_H1S;
    float* xh  = sm + SMEM_XH;
    float* ws  = sm + SMEM_WS;

    const int tid = threadIdx.x;
    const int tx = tid & 63;        // n-group: 64 groups x 8 n = 512-wide chunk
    const int ty = tid >> 6;        // m-group: 4 groups x 8 m = 32 rows
    const int slot0 = blockIdx.x * TM;

    // locate expert segment
    int e = -1, cnt = 0;
#pragma unroll
    for (int ee = 0; ee < NE; ee++) {
        int off = g_offset[ee];
        int pc  = (g_count[ee] + TM - 1) & ~(TM - 1);
        if (slot0 >= off && slot0 < off + pc) { e = ee; cnt = g_count[ee]; }
    }
    if (e < 0) return;
    const int rowsv = min(TM, cnt - (slot0 - g_offset[e]));

    // ---- load gathered x tile into xh[k][m] ----
    for (int idx = tid; idx < TM * (IN_DIM/4); idx += 256) {
        int r = idx / (IN_DIM/4);
        int c4 = idx % (IN_DIM/4);
        float4 v = make_float4(0.f,0.f,0.f,0.f);
        if (r < rowsv) {
            int tok = g_slot_token[slot0 + r];
            v = *(const float4*)(x + (size_t)tok * IN_DIM + c4*4);
        }
        xh[(c4*4+0)*XH_STRIDE + r] = v.x;
        xh[(c4*4+1)*XH_STRIDE + r] = v.y;
        xh[(c4*4+2)*XH_STRIDE + r] = v.z;
        xh[(c4*4+3)*XH_STRIDE + r] = v.w;
    }
    __syncthreads();

    const float* W1e = W1 + (size_t)e * IN_DIM * HD1;
    const float* W2e = W2 + (size_t)e * HD1 * HD2;
    const int kr = tid >> 7;            // staging: rows 0..1 base (2 rows/256 thr pass)
    const int c4s = (tid & 127) * 4;    // 128 float4 per 512-row

    // ================= stage A: h1 = relu(x @ W1 + b1) =================
    for (int n0 = 0; n0 < HD1; n0 += 512) {
        ull acc[4][8];
#pragma unroll
        for (int u = 0; u < 4; u++)
#pragma unroll
            for (int j = 0; j < 8; j++) acc[u][j] = 0ull;

        // prefetch chunk 0 into regs
        float4 pf[4];
#pragma unroll
        for (int i = 0; i < 4; i++)
            pf[i] = *(const float4*)(W1e + (size_t)(kr + i*2) * HD1 + n0 + c4s);

        for (int k0 = 0; k0 < IN_DIM; k0 += KCH) {
            __syncthreads();               // ws consumers of prev chunk done
#pragma unroll
            for (int i = 0; i < 4; i++)
                *(float4*)(ws + (kr + i*2)*512 + c4s) = pf[i];
            __syncthreads();
            if (k0 + KCH < IN_DIM) {
#pragma unroll
                for (int i = 0; i < 4; i++)
                    pf[i] = *(const float4*)(W1e + (size_t)(k0 + KCH + kr + i*2) * HD1 + n0 + c4s);
            }
#pragma unroll
            for (int kk = 0; kk < KCH; kk++) {
                const float* wrow = ws + kk*512 + tx*8;
                float4 b0 = *(const float4*)(wrow);
                float4 b4 = *(const float4*)(wrow + 4);
                ull bs[8];
                bs[0]=splat2(b0.x); bs[1]=splat2(b0.y); bs[2]=splat2(b0.z); bs[3]=splat2(b0.w);
                bs[4]=splat2(b4.x); bs[5]=splat2(b4.y); bs[6]=splat2(b4.z); bs[7]=splat2(b4.w);
                const float* arow = xh + (k0+kk)*XH_STRIDE + ty*8;
                ull a2[4];
#pragma unroll
                for (int u = 0; u < 4; u++) a2[u] = *(const ull*)(arow + 2*u);
#pragma unroll
                for (int j = 0; j < 8; j++)
#pragma unroll
                    for (int u = 0; u < 4; u++) ffma2(acc[u][j], a2[u], bs[j]);
            }
        }
        const float* bb = b1 + (size_t)e * HD1 + n0 + tx*8;
#pragma unroll
        for (int j = 0; j < 8; j++) {
            float bj = bb[j];
            float* hr = h1s + (size_t)(n0 + tx*8 + j) * H1S_STRIDE + ty*8;
#pragma unroll
            for (int u = 0; u < 4; u++) {
                float lo, hi; unpack2(lo, hi, acc[u][j]);
                hr[2*u+0] = fmaxf(lo + bj, 0.f);
                hr[2*u+1] = fmaxf(hi + bj, 0.f);
            }
        }
    }
    __syncthreads();

    // ================= stage B: h2 = relu(h1 @ W2 + b2) =================
    {
        ull acc[4][8];
#pragma unroll
        for (int u = 0; u < 4; u++)
#pragma unroll
            for (int j = 0; j < 8; j++) acc[u][j] = 0ull;

        float4 pf[4];
#pragma unroll
        for (int i = 0; i < 4; i++)
            pf[i] = *(const float4*)(W2e + (size_t)(kr + i*2) * HD2 + c4s);

        for (int k0 = 0; k0 < HD1; k0 += KCH) {
            __syncthreads();
#pragma unroll
            for (int i = 0; i < 4; i++)
                *(float4*)(ws + (kr + i*2)*512 + c4s) = pf[i];
            __syncthreads();
            if (k0 + KCH < HD1) {
#pragma unroll
                for (int i = 0; i < 4; i++)
                    pf[i] = *(const float4*)(W2e + (size_t)(k0 + KCH + kr + i*2) * HD2 + c4s);
            }
#pragma unroll
            for (int kk = 0; kk < KCH; kk++) {
                const float* wrow = ws + kk*512 + tx*8;
                float4 b0 = *(const float4*)(wrow);
                float4 b4 = *(const float4*)(wrow + 4);
                ull bs[8];
                bs[0]=splat2(b0.x); bs[1]=splat2(b0.y); bs[2]=splat2(b0.z); bs[3]=splat2(b0.w);
                bs[4]=splat2(b4.x); bs[5]=splat2(b4.y); bs[6]=splat2(b4.z); bs[7]=splat2(b4.w);
                const float* arow = h1s + (size_t)(k0+kk)*H1S_STRIDE + ty*8;
                ull a2[4];
#pragma unroll
                for (int u = 0; u < 4; u++) a2[u] = *(const ull*)(arow + 2*u);
#pragma unroll
                for (int j = 0; j < 8; j++)
#pragma unroll
                    for (int u = 0; u < 4; u++) ffma2(acc[u][j], a2[u], bs[j]);
            }
        }
        __syncthreads();   // everyone done reading xh (x) before h2 overwrite? (x unused; guards ws too)
        const float* bb = b2 + (size_t)e * HD2 + tx*8;
#pragma unroll
        for (int j = 0; j < 8; j++) {
            float bj = bb[j];
            float* hr = xh + (size_t)(tx*8 + j) * XH_STRIDE + ty*8;
#pragma unroll
            for (int u = 0; u < 4; u++) {
                float lo, hi; unpack2(lo, hi, acc[u][j]);
                hr[2*u+0] = fmaxf(lo + bj, 0.f);
                hr[2*u+1] = fmaxf(hi + bj, 0.f);
            }
        }
    }
    __syncthreads();

    // ===== stage C: eo = h2 @ W3 + b3; combine into out via atomicAdd =====
    const float* W3e = W3 + (size_t)e * HD2 * NC;
    float accC[7];
#pragma unroll
    for (int j = 0; j < 7; j++) accC[j] = 0.f;

    for (int k0 = 0; k0 < HD2; k0 += 64) {
        for (int idx = tid; idx < 64*NC; idx += 256) {
            int krr = idx / NC, c = idx % NC;
            ws[krr*52 + c] = W3e[(size_t)(k0+krr)*NC + c];
        }
        __syncthreads();
#pragma unroll
        for (int j = 0; j < 7; j++) {
            int oi = tid + j*256;
            if (oi < TM*NC) {
                int r = oi / NC, c = oi % NC;
                float s = 0.f;
#pragma unroll 8
                for (int kk = 0; kk < 64; kk++)
                    s += xh[(k0+kk)*XH_STRIDE + r] * ws[kk*52 + c];
                accC[j] += s;
            }
        }
        __syncthreads();
    }
    const float* b3e = b3 + (size_t)e * NC;
#pragma unroll
    for (int j = 0; j < 7; j++) {
        int oi = tid + j*256;
        if (oi < TM*NC) {
            int r = oi / NC, c = oi % NC;
            if (r < rowsv) {
                int tok  = g_slot_token[slot0 + r];
                float v  = g_slot_gate[slot0 + r];
                atomicAdd(&out[(size_t)tok*NC + c], 0.5f * v * (accC[j] + b3e[c]));
            }
        }
    }
}

// ---------------- launch ----------------------------------------------------
extern "C" void kernel_launch(void* const* d_in, const int* in_sizes, int n_in,
                              void* d_out, int out_size) {
    const float* x  = 0; const float* Wr = 0; const float* br = 0;
    const float* W1 = 0; const float* b1 = 0; const float* W2 = 0;
    const float* b2 = 0; const float* W3 = 0; const float* b3 = 0;
    int seen4096 = 0, seen4m = 0;
    for (int i = 0; i < n_in; i++) {
        const float* p = (const float*)d_in[i];
        switch (in_sizes[i]) {
            case 2097152: x  = p; break;
            case 8:       br = p; break;
            case 8192:    b1 = p; break;
            case 204800:  W3 = p; break;
            case 400:     b3 = p; break;
            case 4096:    if (seen4096++ == 0) Wr = p; else b2 = p; break;
            case 4194304: if (seen4m++   == 0) W1 = p; else W2 = p; break;
        }
    }

    float* out       = (float*)d_out;                 // [4096, 50]
    float* out_probs = out + (size_t)BATCH * NC;      // [4096, 8]

    cudaFuncSetAttribute(fused_expert_kernel,
                         cudaFuncAttributeMaxDynamicSharedMemorySize,
                         SMEM_TOTALF * (int)sizeof(float));

    init_kernel<<<1, 32>>>();
    router_kernel<<<BATCH/8, 256>>>(x, Wr, br, out_probs);
    offsets_kernel<<<1, 1>>>();
    fill_kernel<<<(BATCH + 255)/256, 256>>>();
    zero_out_kernel<<<(BATCH*NC + 255)/256, 256>>>(out);
    fused_expert_kernel<<<MAXBLK, 256, SMEM_TOTALF * sizeof(float)>>>(
        x, W1, b1, W2, b2, W3, b3, out);
}